// round 4
// baseline (speedup 1.0000x reference)
#include <cuda_runtime.h>
#include <cuda_bf16.h>
#include <math_constants.h>

#define N_MAX 30000
#define M_MAX 10000

// Scratch (no cudaMalloc allowed -> __device__ globals).
__device__ unsigned long long g_row_best[N_MAX];   // packed (sortkey(s)<<32)|argmin_j
__device__ unsigned int       g_col_best[M_MAX];   // sortkey(s)
#define NB_RED 120
__device__ float g_partials[NB_RED];

// ---------------------------------------------------------------------------
// Packed f32x2 helpers
// ---------------------------------------------------------------------------
__device__ __forceinline__ unsigned long long pack2(float x, float y) {
    unsigned long long r;
    asm("mov.b64 %0, {%1, %2};" : "=l"(r) : "f"(x), "f"(y));
    return r;
}
__device__ __forceinline__ void unpack2(unsigned long long v, float& x, float& y) {
    asm("mov.b64 {%0, %1}, %2;" : "=f"(x), "=f"(y) : "l"(v));
}
__device__ __forceinline__ unsigned long long fma2(unsigned long long a,
                                                   unsigned long long b,
                                                   unsigned long long c) {
    unsigned long long d;
    asm("fma.rn.f32x2 %0, %1, %2, %3;" : "=l"(d) : "l"(a), "l"(b), "l"(c));
    return d;
}

// Sortable-uint encoding for signed floats
__device__ __forceinline__ unsigned int fkey(float f) {
    unsigned int u = __float_as_uint(f);
    return (u & 0x80000000u) ? ~u : (u | 0x80000000u);
}
__device__ __forceinline__ float funkey(unsigned int k) {
    unsigned int u = (k & 0x80000000u) ? (k & 0x7FFFFFFFu) : ~k;
    return __uint_as_float(u);
}

// ---------------------------------------------------------------------------
__global__ void init_kernel(int n, int m) {
    int i = blockIdx.x * blockDim.x + threadIdx.x;
    if (i < n) g_row_best[i] = 0xFFFFFFFFFFFFFFFFull;
    if (i < m) g_col_best[i] = 0xFFFFFFFFu;
}

// ---------------------------------------------------------------------------
// Tile layout per point-pair k (points q0,q1, c = 0.5*|q|^2):
//   tile[2k]   = (x0, x1, y0, y1)
//   tile[2k+1] = (z0, z1, c0, c1)
// ---------------------------------------------------------------------------
#define PAIRS 512            // 1024 points per tile (16 KB)
#define RROWS 4              // rows (queries) per thread
#define TPB   256
#define ROWS_PER_BLOCK (TPB * RROWS)   // 1024

// Shared tile fill used by both kernels. src = point array, [beg, end) range.
__device__ __forceinline__ void fill_tile(float4* tile, const float* __restrict__ src,
                                          int beg, int end) {
    const int cnt = end - beg;
    const int npair = (cnt + 1) >> 1;
    for (int k = threadIdx.x; k < npair; k += TPB) {
        const int j0 = beg + 2 * k;
        const int j1 = j0 + 1;
        const float* q0 = src + (size_t)j0 * 3;
        float x0 = q0[0], y0 = q0[1], z0 = q0[2];
        float c0 = 0.5f * fmaf(x0, x0, fmaf(y0, y0, z0 * z0));
        float x1 = 0.f, y1 = 0.f, z1 = 0.f, c1v = CUDART_INF_F;
        if (j1 < end) {
            const float* q1 = src + (size_t)j1 * 3;
            x1 = q1[0]; y1 = q1[1]; z1 = q1[2];
            c1v = 0.5f * fmaf(x1, x1, fmaf(y1, y1, z1 * z1));
        }
        tile[2 * k + 0] = make_float4(x0, x1, y0, y1);
        tile[2 * k + 1] = make_float4(z0, z1, c0, c1v);
    }
}

// ---------------------------------------------------------------------------
// o->s: each thread owns RROWS rows of P (strided by TPB), scans a chunk of
// Ps staged once in shared memory.  min s + argmin, merged via u64 atomicMin.
// ---------------------------------------------------------------------------
__global__ __launch_bounds__(TPB)
void kernelA(const float* __restrict__ P, const float* __restrict__ Ps,
             int n, int m, int colChunk) {
    __shared__ float4 tile[2 * PAIRS];

    const int rbase = blockIdx.x * ROWS_PER_BLOCK;
    const int cbeg = blockIdx.y * colChunk;
    const int cend = min(cbeg + colChunk, m);

    int rows[RROWS];
    unsigned long long cx[RROWS], cy[RROWS], cz[RROWS];
    float best0[RROWS], best1[RROWS];
    int bidx0[RROWS], bidx1[RROWS];

    #pragma unroll
    for (int i = 0; i < RROWS; i++) {
        const int row = rbase + i * TPB + threadIdx.x;
        rows[i] = row;
        float px = 0.f, py = 0.f, pz = 0.f;
        if (row < n) {
            px = P[row * 3 + 0];
            py = P[row * 3 + 1];
            pz = P[row * 3 + 2];
        }
        cx[i] = pack2(-px, -px);
        cy[i] = pack2(-py, -py);
        cz[i] = pack2(-pz, -pz);
        best0[i] = CUDART_INF_F;
        best1[i] = CUDART_INF_F;
        bidx0[i] = 0;
        bidx1[i] = 0;
    }

    // colChunk <= 2*PAIRS by construction -> exactly one tile
    fill_tile(tile, Ps, cbeg, cend);
    __syncthreads();

    const int npair = (cend - cbeg + 1) >> 1;
    const ulonglong2* tl = (const ulonglong2*)tile;

    #pragma unroll 4
    for (int k = 0; k < npair; k++) {
        const ulonglong2 t0 = tl[2 * k];       // {x01, y01}
        const ulonglong2 t1 = tl[2 * k + 1];   // {z01, c01}
        const int j0 = cbeg + 2 * k;
        #pragma unroll
        for (int i = 0; i < RROWS; i++) {
            unsigned long long s = fma2(cx[i], t0.x, t1.y);
            s = fma2(cy[i], t0.y, s);
            s = fma2(cz[i], t1.x, s);
            float s0, s1;
            unpack2(s, s0, s1);
            if (s0 < best0[i]) { best0[i] = s0; bidx0[i] = j0; }
            if (s1 < best1[i]) { best1[i] = s1; bidx1[i] = j0 + 1; }
        }
    }

    #pragma unroll
    for (int i = 0; i < RROWS; i++) {
        if (rows[i] < n) {
            float b = best0[i];
            int bj = bidx0[i];
            if (best1[i] < b) { b = best1[i]; bj = bidx1[i]; }
            unsigned long long pk =
                ((unsigned long long)fkey(b) << 32) | (unsigned int)bj;
            atomicMin(&g_row_best[rows[i]], pk);
        }
    }
}

// ---------------------------------------------------------------------------
// s->o: each thread owns RROWS cols of Ps, scans a chunk of P.  min s only.
// ---------------------------------------------------------------------------
__global__ __launch_bounds__(TPB)
void kernelB(const float* __restrict__ P, const float* __restrict__ Ps,
             int n, int m, int rowChunk) {
    __shared__ float4 tile[2 * PAIRS];

    const int cbase = blockIdx.x * ROWS_PER_BLOCK;
    const int rbeg = blockIdx.y * rowChunk;
    const int rend = min(rbeg + rowChunk, n);

    int cols[RROWS];
    unsigned long long cx[RROWS], cy[RROWS], cz[RROWS];
    float best0[RROWS], best1[RROWS];

    #pragma unroll
    for (int i = 0; i < RROWS; i++) {
        const int col = cbase + i * TPB + threadIdx.x;
        cols[i] = col;
        float qx = 0.f, qy = 0.f, qz = 0.f;
        if (col < m) {
            qx = Ps[col * 3 + 0];
            qy = Ps[col * 3 + 1];
            qz = Ps[col * 3 + 2];
        }
        cx[i] = pack2(-qx, -qx);
        cy[i] = pack2(-qy, -qy);
        cz[i] = pack2(-qz, -qz);
        best0[i] = CUDART_INF_F;
        best1[i] = CUDART_INF_F;
    }

    fill_tile(tile, P, rbeg, rend);
    __syncthreads();

    const int npair = (rend - rbeg + 1) >> 1;
    const ulonglong2* tl = (const ulonglong2*)tile;

    #pragma unroll 4
    for (int k = 0; k < npair; k++) {
        const ulonglong2 t0 = tl[2 * k];
        const ulonglong2 t1 = tl[2 * k + 1];
        #pragma unroll
        for (int i = 0; i < RROWS; i++) {
            unsigned long long s = fma2(cx[i], t0.x, t1.y);
            s = fma2(cy[i], t0.y, s);
            s = fma2(cz[i], t1.x, s);
            float s0, s1;
            unpack2(s, s0, s1);
            best0[i] = fminf(best0[i], s0);
            best1[i] = fminf(best1[i], s1);
        }
    }

    #pragma unroll
    for (int i = 0; i < RROWS; i++) {
        if (cols[i] < m) {
            float b = fminf(best0[i], best1[i]);
            atomicMin(&g_col_best[cols[i]], fkey(b));
        }
    }
}

// ---------------------------------------------------------------------------
// Reduction: recover d2 = |point|^2 + 2*s_min; deterministic partials.
// ---------------------------------------------------------------------------
__global__ __launch_bounds__(256)
void reduce_kernel(const float* __restrict__ P, const float* __restrict__ Ps,
                   const float* __restrict__ prob, int n, int m) {
    __shared__ float ssum[256];
    const int stride = gridDim.x * blockDim.x;
    const int tid0 = blockIdx.x * blockDim.x + threadIdx.x;

    float sum = 0.0f;
    for (int i = tid0; i < n; i += stride) {
        unsigned long long pk = g_row_best[i];
        float s = funkey((unsigned int)(pk >> 32));
        int j = (int)(unsigned int)(pk & 0xFFFFFFFFu);
        float px = P[i * 3 + 0], py = P[i * 3 + 1], pz = P[i * 3 + 2];
        float p2 = fmaf(px, px, fmaf(py, py, pz * pz));
        float d2 = fmaf(2.0f, s, p2);
        sum += sqrtf(fmaxf(d2, 0.0f)) * prob[j];
    }
    for (int i = tid0; i < m; i += stride) {
        float s = funkey(g_col_best[i]);
        float qx = Ps[i * 3 + 0], qy = Ps[i * 3 + 1], qz = Ps[i * 3 + 2];
        float q2 = fmaf(qx, qx, fmaf(qy, qy, qz * qz));
        float d2 = fmaf(2.0f, s, q2);
        sum += sqrtf(fmaxf(d2, 0.0f)) * prob[i];
    }

    ssum[threadIdx.x] = sum;
    __syncthreads();
    for (int off = 128; off > 0; off >>= 1) {
        if (threadIdx.x < off) ssum[threadIdx.x] += ssum[threadIdx.x + off];
        __syncthreads();
    }
    if (threadIdx.x == 0) g_partials[blockIdx.x] = ssum[0];
}

__global__ void final_kernel(float* __restrict__ out, int nb) {
    if (threadIdx.x == 0 && blockIdx.x == 0) {
        float s = 0.0f;
        for (int i = 0; i < nb; i++) s += g_partials[i];
        out[0] = s;
    }
}

// ---------------------------------------------------------------------------
// Launch
// ---------------------------------------------------------------------------
extern "C" void kernel_launch(void* const* d_in, const int* in_sizes, int n_in,
                              void* d_out, int out_size) {
    const float* P    = (const float*)d_in[0];
    const float* Ps   = (const float*)d_in[1];
    const float* prob = (const float*)d_in[2];
    float* out = (float*)d_out;

    const int n = in_sizes[0] / 3;   // 30000
    const int m = in_sizes[1] / 3;   // 10000

    {
        int total = max(n, m);
        init_kernel<<<(total + 255) / 256, 256>>>(n, m);
    }

    // o->s: row blocks x column splits.  colChunk must be <= 2*PAIRS (one tile).
    {
        int GY = (m + 2 * PAIRS - 1) / (2 * PAIRS);        // 10
        // bump GY a bit for load balance while keeping chunk <= tile
        while ((m + GY - 1) / GY > 2 * PAIRS) GY++;
        const int colChunk = (m + GY - 1) / GY;            // 1000
        dim3 grid((n + ROWS_PER_BLOCK - 1) / ROWS_PER_BLOCK, GY);
        kernelA<<<grid, TPB>>>(P, Ps, n, m, colChunk);
    }

    // s->o: Ps blocks x row splits.  rowChunk <= 2*PAIRS.
    {
        int GY = (n + 2 * PAIRS - 1) / (2 * PAIRS);        // 30
        while ((n + GY - 1) / GY > 2 * PAIRS) GY++;
        const int rowChunk = (n + GY - 1) / GY;            // 1000
        dim3 grid((m + ROWS_PER_BLOCK - 1) / ROWS_PER_BLOCK, GY);
        kernelB<<<grid, TPB>>>(P, Ps, n, m, rowChunk);
    }

    reduce_kernel<<<NB_RED, 256>>>(P, Ps, prob, n, m);
    final_kernel<<<1, 32>>>(out, NB_RED);
}

// round 5
// speedup vs baseline: 1.3314x; 1.3314x over previous
#include <cuda_runtime.h>
#include <cuda_bf16.h>
#include <math_constants.h>

#define N_MAX 30000
#define M_MAX 10000

// Scratch (no cudaMalloc allowed -> __device__ globals).
__device__ unsigned long long g_row_best[N_MAX];   // packed (sortkey(s)<<32)|argmin_j
__device__ unsigned int       g_col_best[M_MAX];   // sortkey(s)
#define NB_RED 120
__device__ float g_partials[NB_RED];

// ---------------------------------------------------------------------------
// Packed f32x2 helpers
// ---------------------------------------------------------------------------
__device__ __forceinline__ unsigned long long pack2(float x, float y) {
    unsigned long long r;
    asm("mov.b64 %0, {%1, %2};" : "=l"(r) : "f"(x), "f"(y));
    return r;
}
__device__ __forceinline__ void unpack2(unsigned long long v, float& x, float& y) {
    asm("mov.b64 {%0, %1}, %2;" : "=f"(x), "=f"(y) : "l"(v));
}
__device__ __forceinline__ unsigned long long fma2(unsigned long long a,
                                                   unsigned long long b,
                                                   unsigned long long c) {
    unsigned long long d;
    asm("fma.rn.f32x2 %0, %1, %2, %3;" : "=l"(d) : "l"(a), "l"(b), "l"(c));
    return d;
}

// Sortable-uint encoding for signed floats
__device__ __forceinline__ unsigned int fkey(float f) {
    unsigned int u = __float_as_uint(f);
    return (u & 0x80000000u) ? ~u : (u | 0x80000000u);
}
__device__ __forceinline__ float funkey(unsigned int k) {
    unsigned int u = (k & 0x80000000u) ? (k & 0x7FFFFFFFu) : ~k;
    return __uint_as_float(u);
}

// ---------------------------------------------------------------------------
__global__ void init_kernel(int n, int m) {
    int i = blockIdx.x * blockDim.x + threadIdx.x;
    if (i < n) g_row_best[i] = 0xFFFFFFFFFFFFFFFFull;
    if (i < m) g_col_best[i] = 0xFFFFFFFFu;
}

// ---------------------------------------------------------------------------
// Tile layout per point-pair k (points t0,t1, c = 0.5*|t|^2):
//   tile[2k]   = (x0, x1, y0, y1)
//   tile[2k+1] = (z0, z1, c0, c1)
// ---------------------------------------------------------------------------
#define PAIRS   512                 // 1024 points per tile (16 KB smem)
#define TILEPTS (2 * PAIRS)
#define RROWS   4                   // queries per thread
#define TPB     128
#define QPB     (TPB * RROWS)       // 512 queries per block

__device__ __forceinline__ void fill_tile(float4* tile, const float* __restrict__ src,
                                          int beg, int end) {
    const int npair = (end - beg + 1) >> 1;
    for (int k = threadIdx.x; k < npair; k += TPB) {
        const int j0 = beg + 2 * k;
        const int j1 = j0 + 1;
        const float* q0 = src + (size_t)j0 * 3;
        float x0 = q0[0], y0 = q0[1], z0 = q0[2];
        float c0 = 0.5f * fmaf(x0, x0, fmaf(y0, y0, z0 * z0));
        float x1 = 0.f, y1 = 0.f, z1 = 0.f, c1v = CUDART_INF_F;
        if (j1 < end) {
            const float* q1 = src + (size_t)j1 * 3;
            x1 = q1[0]; y1 = q1[1]; z1 = q1[2];
            c1v = 0.5f * fmaf(x1, x1, fmaf(y1, y1, z1 * z1));
        }
        tile[2 * k + 0] = make_float4(x0, x1, y0, y1);
        tile[2 * k + 1] = make_float4(z0, z1, c0, c1v);
    }
}

// ---------------------------------------------------------------------------
// Merged pair kernel.  Flat 1D grid:
//   blocks [0, nItemsA)          : o->s items (queries = P rows, targets = Ps)
//   blocks [nItemsA, nItemsA+NB) : s->o items (queries = Ps cols, targets = P)
// Each item: 512 queries x <=1024 targets, one smem tile, one barrier.
// ---------------------------------------------------------------------------
__global__ __launch_bounds__(TPB)
void pairs_kernel(const float* __restrict__ P, const float* __restrict__ Ps,
                  int n, int m, int nItemsA, int gyA, int gyB) {
    __shared__ float4 tile[2 * PAIRS];

    const int bid = blockIdx.x;
    const bool isA = (bid < nItemsA);

    const float* qsrc; const float* tsrc;
    int qn, qbase, tbeg, tend;
    if (isA) {
        const int rg = bid / gyA;
        const int ch = bid - rg * gyA;
        qsrc = P;  qn = n; qbase = rg * QPB;
        tsrc = Ps; tbeg = ch * TILEPTS; tend = min(tbeg + TILEPTS, m);
    } else {
        const int b = bid - nItemsA;
        const int cg = b / gyB;
        const int ch = b - cg * gyB;
        qsrc = Ps; qn = m; qbase = cg * QPB;
        tsrc = P;  tbeg = ch * TILEPTS; tend = min(tbeg + TILEPTS, n);
    }

    int rows[RROWS];
    unsigned long long cx[RROWS], cy[RROWS], cz[RROWS];
    float best0[RROWS], best1[RROWS];
    int bidx0[RROWS], bidx1[RROWS];

    #pragma unroll
    for (int i = 0; i < RROWS; i++) {
        const int row = qbase + i * TPB + threadIdx.x;
        rows[i] = row;
        float px = 0.f, py = 0.f, pz = 0.f;
        if (row < qn) {
            px = qsrc[row * 3 + 0];
            py = qsrc[row * 3 + 1];
            pz = qsrc[row * 3 + 2];
        }
        cx[i] = pack2(-px, -px);
        cy[i] = pack2(-py, -py);
        cz[i] = pack2(-pz, -pz);
        best0[i] = CUDART_INF_F;
        best1[i] = CUDART_INF_F;
        bidx0[i] = 0;
        bidx1[i] = 0;
    }

    fill_tile(tile, tsrc, tbeg, tend);
    __syncthreads();

    const int npair = (tend - tbeg + 1) >> 1;
    const ulonglong2* tl = (const ulonglong2*)tile;

    if (isA) {
        // min + argmin
        #pragma unroll 4
        for (int k = 0; k < npair; k++) {
            const ulonglong2 t0 = tl[2 * k];       // {x01, y01}
            const ulonglong2 t1 = tl[2 * k + 1];   // {z01, c01}
            const int j0 = tbeg + 2 * k;
            #pragma unroll
            for (int i = 0; i < RROWS; i++) {
                unsigned long long s = fma2(cx[i], t0.x, t1.y);
                s = fma2(cy[i], t0.y, s);
                s = fma2(cz[i], t1.x, s);
                float s0, s1;
                unpack2(s, s0, s1);
                if (s0 < best0[i]) { best0[i] = s0; bidx0[i] = j0; }
                if (s1 < best1[i]) { best1[i] = s1; bidx1[i] = j0 + 1; }
            }
        }
        #pragma unroll
        for (int i = 0; i < RROWS; i++) {
            if (rows[i] < qn) {
                float b = best0[i];
                int bj = bidx0[i];
                if (best1[i] < b) { b = best1[i]; bj = bidx1[i]; }
                unsigned long long pk =
                    ((unsigned long long)fkey(b) << 32) | (unsigned int)bj;
                atomicMin(&g_row_best[rows[i]], pk);
            }
        }
    } else {
        // min only
        #pragma unroll 4
        for (int k = 0; k < npair; k++) {
            const ulonglong2 t0 = tl[2 * k];
            const ulonglong2 t1 = tl[2 * k + 1];
            #pragma unroll
            for (int i = 0; i < RROWS; i++) {
                unsigned long long s = fma2(cx[i], t0.x, t1.y);
                s = fma2(cy[i], t0.y, s);
                s = fma2(cz[i], t1.x, s);
                float s0, s1;
                unpack2(s, s0, s1);
                best0[i] = fminf(best0[i], s0);
                best1[i] = fminf(best1[i], s1);
            }
        }
        #pragma unroll
        for (int i = 0; i < RROWS; i++) {
            if (rows[i] < qn) {
                float b = fminf(best0[i], best1[i]);
                atomicMin(&g_col_best[rows[i]], fkey(b));
            }
        }
    }
}

// ---------------------------------------------------------------------------
// Reduction: recover d2 = |point|^2 + 2*s_min; deterministic partials.
// ---------------------------------------------------------------------------
__global__ __launch_bounds__(256)
void reduce_kernel(const float* __restrict__ P, const float* __restrict__ Ps,
                   const float* __restrict__ prob, int n, int m) {
    __shared__ float ssum[256];
    const int stride = gridDim.x * blockDim.x;
    const int tid0 = blockIdx.x * blockDim.x + threadIdx.x;

    float sum = 0.0f;
    for (int i = tid0; i < n; i += stride) {
        unsigned long long pk = g_row_best[i];
        float s = funkey((unsigned int)(pk >> 32));
        int j = (int)(unsigned int)(pk & 0xFFFFFFFFu);
        float px = P[i * 3 + 0], py = P[i * 3 + 1], pz = P[i * 3 + 2];
        float p2 = fmaf(px, px, fmaf(py, py, pz * pz));
        float d2 = fmaf(2.0f, s, p2);
        sum += sqrtf(fmaxf(d2, 0.0f)) * prob[j];
    }
    for (int i = tid0; i < m; i += stride) {
        float s = funkey(g_col_best[i]);
        float qx = Ps[i * 3 + 0], qy = Ps[i * 3 + 1], qz = Ps[i * 3 + 2];
        float q2 = fmaf(qx, qx, fmaf(qy, qy, qz * qz));
        float d2 = fmaf(2.0f, s, q2);
        sum += sqrtf(fmaxf(d2, 0.0f)) * prob[i];
    }

    ssum[threadIdx.x] = sum;
    __syncthreads();
    for (int off = 128; off > 0; off >>= 1) {
        if (threadIdx.x < off) ssum[threadIdx.x] += ssum[threadIdx.x + off];
        __syncthreads();
    }
    if (threadIdx.x == 0) g_partials[blockIdx.x] = ssum[0];
}

__global__ void final_kernel(float* __restrict__ out, int nb) {
    if (threadIdx.x == 0 && blockIdx.x == 0) {
        float s = 0.0f;
        for (int i = 0; i < nb; i++) s += g_partials[i];
        out[0] = s;
    }
}

// ---------------------------------------------------------------------------
// Launch
// ---------------------------------------------------------------------------
extern "C" void kernel_launch(void* const* d_in, const int* in_sizes, int n_in,
                              void* d_out, int out_size) {
    const float* P    = (const float*)d_in[0];
    const float* Ps   = (const float*)d_in[1];
    const float* prob = (const float*)d_in[2];
    float* out = (float*)d_out;

    const int n = in_sizes[0] / 3;   // 30000
    const int m = in_sizes[1] / 3;   // 10000

    {
        int total = max(n, m);
        init_kernel<<<(total + 255) / 256, 256>>>(n, m);
    }

    // Work-item enumeration for the merged kernel.
    const int gyA = (m + TILEPTS - 1) / TILEPTS;               // 10
    const int rgA = (n + QPB - 1) / QPB;                       // 59
    const int nItemsA = rgA * gyA;                             // 590

    const int gyB = (n + TILEPTS - 1) / TILEPTS;               // 30
    const int cgB = (m + QPB - 1) / QPB;                       // 20
    const int nItemsB = cgB * gyB;                             // 600

    pairs_kernel<<<nItemsA + nItemsB, TPB>>>(P, Ps, n, m, nItemsA, gyA, gyB);

    reduce_kernel<<<NB_RED, 256>>>(P, Ps, prob, n, m);
    final_kernel<<<1, 32>>>(out, NB_RED);
}